// round 11
// baseline (speedup 1.0000x reference)
#include <cuda_runtime.h>
#include <math.h>

#define LSEQ   4096
#define DCH    768
#define NBATCH 8
#define NBLK   8
#define BS     96
#define NMODES 2049   // LSEQ/2 + 1
#define MP     2064   // padded mode stride
#define MT     128    // mode tile in MLP kernel
#define LAMBDA 0.01f
#define PAIRS_PER_CTA 4
#define MLP_THREADS 512

// Scratch spectra: (B, D, MP) real and imag
__device__ float g_Sr[(size_t)NBATCH * DCH * MP];
__device__ float g_Si[(size_t)NBATCH * DCH * MP];

extern __shared__ char smem_raw[];

// ---------------- packed f32x2 helpers (FFMA2 path) ----------------
typedef unsigned long long ull;

__device__ __forceinline__ ull bcast2(float v) {
    ull r; asm("mov.b64 %0, {%1, %1};" : "=l"(r) : "f"(v)); return r;
}
__device__ __forceinline__ void unpack2(ull a, float& lo, float& hi) {
    asm("mov.b64 {%0, %1}, %2;" : "=f"(lo), "=f"(hi) : "l"(a));
}
__device__ __forceinline__ void ffma2(ull& d, ull a, ull b) {
    asm("fma.rn.f32x2 %0, %1, %2, %0;" : "+l"(d) : "l"(a), "l"(b));
}

// ---------------------------------------------------------------------------
// Forward FFT (R9-proven): 4 channel-pairs per CTA, 1024 threads.
// Radix-2 Stockham, 12 stages, single buffer per pair (read/sync/write).
// ---------------------------------------------------------------------------
__global__ __launch_bounds__(1024) void fwd_fft_kernel(const float* __restrict__ x) {
    float2* buf = reinterpret_cast<float2*>(smem_raw);       // [4][4096]
    float2* tw  = buf + PAIRS_PER_CTA * LSEQ;                // [2048]
    const int tid = threadIdx.x;
    const int sub = tid >> 8;
    const int st  = tid & 255;
    const int bi  = blockIdx.x;
    const int b   = bi / (DCH / 8);
    const int c0  = (bi % (DCH / 8)) * 8;

    for (int j = tid; j < LSEQ / 2; j += 1024) {
        float sv, cv;
        sincosf(-6.28318530717958647692f * (float)j / (float)LSEQ, &sv, &cv);
        tw[j] = make_float2(cv, sv);
    }
    const float* xs = x + (size_t)b * LSEQ * DCH + c0;
    for (int i = tid; i < LSEQ * 2; i += 1024) {
        int l = i >> 1, h = i & 1;
        float4 v = *reinterpret_cast<const float4*>(xs + (size_t)l * DCH + h * 4);
        buf[(2 * h)     * LSEQ + l] = make_float2(v.x, v.y);
        buf[(2 * h + 1) * LSEQ + l] = make_float2(v.z, v.w);
    }
    __syncthreads();

    float2* bp = buf + sub * LSEQ;
    for (int ls = 0; ls < 12; ls++) {
        const int s = 1 << ls;
        float2 a[8], c[8];
        #pragma unroll
        for (int k = 0; k < 8; k++) {
            int bt = st + (k << 8);
            a[k] = bp[bt];
            c[k] = bp[bt + 2048];
        }
        __syncthreads();
        #pragma unroll
        for (int k = 0; k < 8; k++) {
            int bt = st + (k << 8);
            int r  = bt & ~(s - 1);
            float2 w = tw[r];
            float dx = a[k].x - c[k].x, dy = a[k].y - c[k].y;
            int o = bt + r;
            bp[o]     = make_float2(a[k].x + c[k].x, a[k].y + c[k].y);
            bp[o + s] = make_float2(dx * w.x - dy * w.y, dx * w.y + dy * w.x);
        }
        __syncthreads();
    }
    const int d0 = c0 + 2 * sub;
    const float scale = 0.5f / 64.0f;
    float* SrB = g_Sr + ((size_t)b * DCH + d0) * MP;
    float* SiB = g_Si + ((size_t)b * DCH + d0) * MP;
    for (int k = st; k < NMODES; k += 256) {
        float2 z1 = bp[k];
        float2 z2 = bp[(LSEQ - k) & (LSEQ - 1)];
        SrB[k]      = (z1.x + z2.x) * scale;
        SiB[k]      = (z1.y - z2.y) * scale;
        SrB[MP + k] = (z1.y + z2.y) * scale;
        SiB[MP + k] = (z2.x - z1.x) * scale;
    }
}

// ---------------------------------------------------------------------------
// Inverse FFT (R9-proven): same structure, conjugate twiddles, residual add.
// ---------------------------------------------------------------------------
__global__ __launch_bounds__(1024) void inv_fft_kernel(const float* __restrict__ x,
                                                       float* __restrict__ y) {
    float2* buf = reinterpret_cast<float2*>(smem_raw);
    float2* tw  = buf + PAIRS_PER_CTA * LSEQ;
    const int tid = threadIdx.x;
    const int sub = tid >> 8;
    const int st  = tid & 255;
    const int bi  = blockIdx.x;
    const int b   = bi / (DCH / 8);
    const int c0  = (bi % (DCH / 8)) * 8;
    const int d0  = c0 + 2 * sub;

    for (int j = tid; j < LSEQ / 2; j += 1024) {
        float sv, cv;
        sincosf(6.28318530717958647692f * (float)j / (float)LSEQ, &sv, &cv);
        tw[j] = make_float2(cv, sv);
    }
    float2* bp = buf + sub * LSEQ;
    const float* SrB = g_Sr + ((size_t)b * DCH + d0) * MP;
    const float* SiB = g_Si + ((size_t)b * DCH + d0) * MP;
    for (int k = st; k < NMODES; k += 256) {
        float ar  = SrB[k],      ai  = SiB[k];
        float br  = SrB[MP + k], bi_ = SiB[MP + k];
        if (k == 0 || k == LSEQ / 2) { ai = 0.0f; bi_ = 0.0f; }
        bp[k] = make_float2(ar - bi_, ai + br);
        if (k > 0 && k < LSEQ / 2)
            bp[LSEQ - k] = make_float2(ar + bi_, br - ai);
    }
    __syncthreads();

    for (int ls = 0; ls < 12; ls++) {
        const int s = 1 << ls;
        float2 a[8], c[8];
        #pragma unroll
        for (int k = 0; k < 8; k++) {
            int bt = st + (k << 8);
            a[k] = bp[bt];
            c[k] = bp[bt + 2048];
        }
        __syncthreads();
        #pragma unroll
        for (int k = 0; k < 8; k++) {
            int bt = st + (k << 8);
            int r  = bt & ~(s - 1);
            float2 w = tw[r];
            float dx = a[k].x - c[k].x, dy = a[k].y - c[k].y;
            int o = bt + r;
            bp[o]     = make_float2(a[k].x + c[k].x, a[k].y + c[k].y);
            bp[o + s] = make_float2(dx * w.x - dy * w.y, dx * w.y + dy * w.x);
        }
        __syncthreads();
    }
    const float sc = 1.0f / 64.0f;
    const float* xs = x + (size_t)b * LSEQ * DCH + c0;
    float*       ys = y + (size_t)b * LSEQ * DCH + c0;
    for (int i = tid; i < LSEQ * 2; i += 1024) {
        int l = i >> 1, h = i & 1;
        float2 u  = buf[(2 * h)     * LSEQ + l];
        float2 v2 = buf[(2 * h + 1) * LSEQ + l];
        float4 xv = *reinterpret_cast<const float4*>(xs + (size_t)l * DCH + h * 4);
        float4 out = make_float4(xv.x + u.x * sc,  xv.y + u.y * sc,
                                 xv.z + v2.x * sc, xv.w + v2.y * sc);
        *reinterpret_cast<float4*>(ys + (size_t)l * DCH + h * 4) = out;
    }
}

// ---------------------------------------------------------------------------
// Per-mode complex block-diagonal MLP, packed f32x2 FMA, 512 threads.
// Grid: (17 mode-tiles, 8 blocks, 8 batch). 16 warps/CTA (4/SMSP).
// lane = tid&15 -> modes lane*8..+7 (4 pairs); og = tid>>4 (0..31) ->
// outputs {og, og+32, og+64} (stride 32, aligned W reads).
// Per K-step: 48 FFMA2 + 4 LDS.128 + 6 LDS.32 + 6 bcast + 4 XOR.
// Smem: W (72KB) + X/O1 (96KB) = 168KB, 1 CTA/SM.
// ---------------------------------------------------------------------------
__global__ __launch_bounds__(MLP_THREADS) void mlp_kernel(const float* __restrict__ w1,
                                                          const float* __restrict__ b1,
                                                          const float* __restrict__ w2,
                                                          const float* __restrict__ b2) {
    float* Wr = reinterpret_cast<float*>(smem_raw);    // [96][96]
    float* Wi = Wr + BS * BS;
    float* Xr = Wi + BS * BS;                          // [96][128], reused for O1
    float* Xi = Xr + BS * MT;

    const int tid  = threadIdx.x;
    const int n    = blockIdx.y;
    const int b    = blockIdx.z;
    const int m0   = blockIdx.x * MT;
    const int lane = tid & 15;
    const int og   = tid >> 4;          // 0..31, outputs og + 32*oo
    const bool full = (m0 + MT <= NMODES);

    // stage W1 (layout w1[c][n][i][o])
    {
        const float4* w1r4 = reinterpret_cast<const float4*>(w1 + (size_t)n * BS * BS);
        const float4* w1i4 = reinterpret_cast<const float4*>(w1 + (size_t)(NBLK + n) * BS * BS);
        for (int t = tid; t < BS * BS / 4; t += MLP_THREADS) {
            reinterpret_cast<float4*>(Wr)[t] = w1r4[t];
            reinterpret_cast<float4*>(Wi)[t] = w1i4[t];
        }
    }
    float* SrB = g_Sr + ((size_t)b * DCH + n * BS) * MP;
    float* SiB = g_Si + ((size_t)b * DCH + n * BS) * MP;
    for (int t = tid; t < BS * (MT / 4); t += MLP_THREADS) {
        int i = t >> 5, c = t & 31;
        int m = m0 + c * 4;
        float4 vr, vi;
        if (full) {
            vr = *reinterpret_cast<const float4*>(SrB + (size_t)i * MP + m);
            vi = *reinterpret_cast<const float4*>(SiB + (size_t)i * MP + m);
        } else {
            vr = make_float4(0.f, 0.f, 0.f, 0.f);
            vi = make_float4(0.f, 0.f, 0.f, 0.f);
            #pragma unroll
            for (int j = 0; j < 4; j++) {
                if (m + j < NMODES) {
                    (&vr.x)[j] = SrB[(size_t)i * MP + m + j];
                    (&vi.x)[j] = SiB[(size_t)i * MP + m + j];
                }
            }
        }
        *reinterpret_cast<float4*>(Xr + i * MT + c * 4) = vr;
        *reinterpret_cast<float4*>(Xi + i * MT + c * 4) = vi;
    }
    __syncthreads();

    const ull SGN2 = 0x8000000080000000ULL;

    // ---------------- layer 1 ----------------
    ull accR[3][4], accI[3][4];   // [oo][mode-pair], output = og + 32*oo
    {
        const float* b1r = b1 + (size_t)n * BS + og;
        const float* b1i = b1 + (size_t)(NBLK + n) * BS + og;
        #pragma unroll
        for (int oo = 0; oo < 3; oo++) {
            ull vr = bcast2(b1r[32 * oo]), vi = bcast2(b1i[32 * oo]);
            #pragma unroll
            for (int j = 0; j < 4; j++) { accR[oo][j] = vr; accI[oo][j] = vi; }
        }
    }
    {
        const float* xrp = Xr + lane * 8;
        const float* xip = Xi + lane * 8;
        const float* wrp = Wr + og;
        const float* wip = Wi + og;
        #pragma unroll 2
        for (int i = 0; i < BS; i++) {
            ulonglong2 xra = *reinterpret_cast<const ulonglong2*>(xrp + i * MT);
            ulonglong2 xrb = *reinterpret_cast<const ulonglong2*>(xrp + i * MT + 4);
            ulonglong2 xia = *reinterpret_cast<const ulonglong2*>(xip + i * MT);
            ulonglong2 xib = *reinterpret_cast<const ulonglong2*>(xip + i * MT + 4);
            ull xr_[4] = {xra.x, xra.y, xrb.x, xrb.y};
            ull xi_[4] = {xia.x, xia.y, xib.x, xib.y};
            ull nxi[4] = {xia.x ^ SGN2, xia.y ^ SGN2, xib.x ^ SGN2, xib.y ^ SGN2};
            #pragma unroll
            for (int oo = 0; oo < 3; oo++) {
                ull w_r = bcast2(wrp[i * BS + 32 * oo]);
                ull w_i = bcast2(wip[i * BS + 32 * oo]);
                #pragma unroll
                for (int j = 0; j < 4; j++) {
                    ffma2(accR[oo][j], w_r, xr_[j]); ffma2(accR[oo][j], w_i, nxi[j]);
                    ffma2(accI[oo][j], w_r, xi_[j]); ffma2(accI[oo][j], w_i, xr_[j]);
                }
            }
        }
    }
    __syncthreads();   // all X / W1 reads done

    // relu -> O1 (into X buffer); stage W2
    #pragma unroll
    for (int oo = 0; oo < 3; oo++) {
        int row = og + 32 * oo;
        float r[8], im[8];
        #pragma unroll
        for (int j = 0; j < 4; j++) {
            unpack2(accR[oo][j], r[2 * j], r[2 * j + 1]);
            unpack2(accI[oo][j], im[2 * j], im[2 * j + 1]);
        }
        *reinterpret_cast<float4*>(Xr + row * MT + lane * 8) =
            make_float4(fmaxf(r[0], 0.f), fmaxf(r[1], 0.f), fmaxf(r[2], 0.f), fmaxf(r[3], 0.f));
        *reinterpret_cast<float4*>(Xr + row * MT + lane * 8 + 4) =
            make_float4(fmaxf(r[4], 0.f), fmaxf(r[5], 0.f), fmaxf(r[6], 0.f), fmaxf(r[7], 0.f));
        *reinterpret_cast<float4*>(Xi + row * MT + lane * 8) =
            make_float4(fmaxf(im[0], 0.f), fmaxf(im[1], 0.f), fmaxf(im[2], 0.f), fmaxf(im[3], 0.f));
        *reinterpret_cast<float4*>(Xi + row * MT + lane * 8 + 4) =
            make_float4(fmaxf(im[4], 0.f), fmaxf(im[5], 0.f), fmaxf(im[6], 0.f), fmaxf(im[7], 0.f));
    }
    {
        const float4* w2r4 = reinterpret_cast<const float4*>(w2 + (size_t)n * BS * BS);
        const float4* w2i4 = reinterpret_cast<const float4*>(w2 + (size_t)(NBLK + n) * BS * BS);
        for (int t = tid; t < BS * BS / 4; t += MLP_THREADS) {
            reinterpret_cast<float4*>(Wr)[t] = w2r4[t];
            reinterpret_cast<float4*>(Wi)[t] = w2i4[t];
        }
    }
    __syncthreads();

    // ---------------- layer 2 ----------------
    {
        const float* b2r = b2 + (size_t)n * BS + og;
        const float* b2i = b2 + (size_t)(NBLK + n) * BS + og;
        #pragma unroll
        for (int oo = 0; oo < 3; oo++) {
            ull vr = bcast2(b2r[32 * oo]), vi = bcast2(b2i[32 * oo]);
            #pragma unroll
            for (int j = 0; j < 4; j++) { accR[oo][j] = vr; accI[oo][j] = vi; }
        }
    }
    {
        const float* xrp = Xr + lane * 8;
        const float* xip = Xi + lane * 8;
        const float* wrp = Wr + og;
        const float* wip = Wi + og;
        #pragma unroll 2
        for (int o = 0; o < BS; o++) {
            ulonglong2 xra = *reinterpret_cast<const ulonglong2*>(xrp + o * MT);
            ulonglong2 xrb = *reinterpret_cast<const ulonglong2*>(xrp + o * MT + 4);
            ulonglong2 xia = *reinterpret_cast<const ulonglong2*>(xip + o * MT);
            ulonglong2 xib = *reinterpret_cast<const ulonglong2*>(xip + o * MT + 4);
            ull xr_[4] = {xra.x, xra.y, xrb.x, xrb.y};
            ull xi_[4] = {xia.x, xia.y, xib.x, xib.y};
            ull nxi[4] = {xia.x ^ SGN2, xia.y ^ SGN2, xib.x ^ SGN2, xib.y ^ SGN2};
            #pragma unroll
            for (int oo = 0; oo < 3; oo++) {
                ull w_r = bcast2(wrp[o * BS + 32 * oo]);
                ull w_i = bcast2(wip[o * BS + 32 * oo]);
                #pragma unroll
                for (int j = 0; j < 4; j++) {
                    ffma2(accR[oo][j], w_r, xr_[j]); ffma2(accR[oo][j], w_i, nxi[j]);
                    ffma2(accI[oo][j], w_r, xi_[j]); ffma2(accI[oo][j], w_i, xr_[j]);
                }
            }
        }
    }

    // softshrink + store
    #pragma unroll
    for (int oo = 0; oo < 3; oo++) {
        int row = og + 32 * oo;
        float v[16];
        #pragma unroll
        for (int j = 0; j < 4; j++) {
            unpack2(accR[oo][j], v[2 * j], v[2 * j + 1]);
            unpack2(accI[oo][j], v[8 + 2 * j], v[9 + 2 * j]);
        }
        #pragma unroll
        for (int j = 0; j < 16; j++) {
            float t = fabsf(v[j]) - LAMBDA;
            v[j] = t > 0.f ? copysignf(t, v[j]) : 0.f;
        }
        int m = m0 + lane * 8;
        if (full) {
            *reinterpret_cast<float4*>(SrB + (size_t)row * MP + m)     = make_float4(v[0], v[1], v[2], v[3]);
            *reinterpret_cast<float4*>(SrB + (size_t)row * MP + m + 4) = make_float4(v[4], v[5], v[6], v[7]);
            *reinterpret_cast<float4*>(SiB + (size_t)row * MP + m)     = make_float4(v[8], v[9], v[10], v[11]);
            *reinterpret_cast<float4*>(SiB + (size_t)row * MP + m + 4) = make_float4(v[12], v[13], v[14], v[15]);
        } else {
            #pragma unroll
            for (int j = 0; j < 8; j++) {
                if (m + j < NMODES) {
                    SrB[(size_t)row * MP + m + j] = v[j];
                    SiB[(size_t)row * MP + m + j] = v[8 + j];
                }
            }
        }
    }
}

// ---------------------------------------------------------------------------
extern "C" void kernel_launch(void* const* d_in, const int* in_sizes, int n_in,
                              void* d_out, int out_size) {
    const float* x  = (const float*)d_in[0];
    const float* w1 = (const float*)d_in[1];
    const float* b1 = (const float*)d_in[2];
    const float* w2 = (const float*)d_in[3];
    const float* b2 = (const float*)d_in[4];
    float* y = (float*)d_out;

    const size_t fft_smem = (size_t)(PAIRS_PER_CTA * LSEQ + LSEQ / 2) * sizeof(float2); // 147456
    const size_t mlp_smem = (size_t)(2 * BS * BS + 2 * BS * MT) * sizeof(float);        // 172032

    cudaFuncSetAttribute(fwd_fft_kernel, cudaFuncAttributeMaxDynamicSharedMemorySize, (int)fft_smem);
    cudaFuncSetAttribute(inv_fft_kernel, cudaFuncAttributeMaxDynamicSharedMemorySize, (int)fft_smem);
    cudaFuncSetAttribute(mlp_kernel,     cudaFuncAttributeMaxDynamicSharedMemorySize, (int)mlp_smem);

    fwd_fft_kernel<<<NBATCH * DCH / 8, 1024, fft_smem>>>(x);

    dim3 g((NMODES + MT - 1) / MT, NBLK, NBATCH);
    mlp_kernel<<<g, MLP_THREADS, mlp_smem>>>(w1, b1, w2, b2);

    inv_fft_kernel<<<NBATCH * DCH / 8, 1024, fft_smem>>>(x, y);
}

// round 13
// speedup vs baseline: 1.1251x; 1.1251x over previous
#include <cuda_runtime.h>
#include <math.h>

#define LSEQ   4096
#define DCH    768
#define NBATCH 8
#define NBLK   8
#define BS     96
#define NMODES 2049   // LSEQ/2 + 1
#define MP     2064   // padded mode stride
#define MT     128    // mode tile in MLP kernel
#define LAMBDA 0.01f
#define PAIRS_PER_CTA 4
#define MLP_THREADS 384

// Scratch spectra: (B, D, MP) real and imag
__device__ float g_Sr[(size_t)NBATCH * DCH * MP];
__device__ float g_Si[(size_t)NBATCH * DCH * MP];

extern __shared__ char smem_raw[];

// ---------------- packed f32x2 helpers (FFMA2 path) ----------------
typedef unsigned long long ull;

__device__ __forceinline__ ull bcast2(float v) {
    ull r; asm("mov.b64 %0, {%1, %1};" : "=l"(r) : "f"(v)); return r;
}
__device__ __forceinline__ void unpack2(ull a, float& lo, float& hi) {
    asm("mov.b64 {%0, %1}, %2;" : "=f"(lo), "=f"(hi) : "l"(a));
}
__device__ __forceinline__ void ffma2(ull& d, ull a, ull b) {
    asm("fma.rn.f32x2 %0, %1, %2, %0;" : "+l"(d) : "l"(a), "l"(b));
}
__device__ __forceinline__ ull fadd2(ull a, ull b) {
    ull r; asm("add.rn.f32x2 %0, %1, %2;" : "=l"(r) : "l"(a), "l"(b)); return r;
}

// ---------------------------------------------------------------------------
// Forward FFT (R9-proven): 4 channel-pairs per CTA, 1024 threads.
// Radix-2 Stockham, 12 stages, single buffer per pair (read/sync/write).
// ---------------------------------------------------------------------------
__global__ __launch_bounds__(1024) void fwd_fft_kernel(const float* __restrict__ x) {
    float2* buf = reinterpret_cast<float2*>(smem_raw);       // [4][4096]
    float2* tw  = buf + PAIRS_PER_CTA * LSEQ;                // [2048]
    const int tid = threadIdx.x;
    const int sub = tid >> 8;
    const int st  = tid & 255;
    const int bi  = blockIdx.x;
    const int b   = bi / (DCH / 8);
    const int c0  = (bi % (DCH / 8)) * 8;

    for (int j = tid; j < LSEQ / 2; j += 1024) {
        float sv, cv;
        sincosf(-6.28318530717958647692f * (float)j / (float)LSEQ, &sv, &cv);
        tw[j] = make_float2(cv, sv);
    }
    const float* xs = x + (size_t)b * LSEQ * DCH + c0;
    for (int i = tid; i < LSEQ * 2; i += 1024) {
        int l = i >> 1, h = i & 1;
        float4 v = *reinterpret_cast<const float4*>(xs + (size_t)l * DCH + h * 4);
        buf[(2 * h)     * LSEQ + l] = make_float2(v.x, v.y);
        buf[(2 * h + 1) * LSEQ + l] = make_float2(v.z, v.w);
    }
    __syncthreads();

    float2* bp = buf + sub * LSEQ;
    for (int ls = 0; ls < 12; ls++) {
        const int s = 1 << ls;
        float2 a[8], c[8];
        #pragma unroll
        for (int k = 0; k < 8; k++) {
            int bt = st + (k << 8);
            a[k] = bp[bt];
            c[k] = bp[bt + 2048];
        }
        __syncthreads();
        #pragma unroll
        for (int k = 0; k < 8; k++) {
            int bt = st + (k << 8);
            int r  = bt & ~(s - 1);
            float2 w = tw[r];
            float dx = a[k].x - c[k].x, dy = a[k].y - c[k].y;
            int o = bt + r;
            bp[o]     = make_float2(a[k].x + c[k].x, a[k].y + c[k].y);
            bp[o + s] = make_float2(dx * w.x - dy * w.y, dx * w.y + dy * w.x);
        }
        __syncthreads();
    }
    const int d0 = c0 + 2 * sub;
    const float scale = 0.5f / 64.0f;
    float* SrB = g_Sr + ((size_t)b * DCH + d0) * MP;
    float* SiB = g_Si + ((size_t)b * DCH + d0) * MP;
    for (int k = st; k < NMODES; k += 256) {
        float2 z1 = bp[k];
        float2 z2 = bp[(LSEQ - k) & (LSEQ - 1)];
        SrB[k]      = (z1.x + z2.x) * scale;
        SiB[k]      = (z1.y - z2.y) * scale;
        SrB[MP + k] = (z1.y + z2.y) * scale;
        SiB[MP + k] = (z2.x - z1.x) * scale;
    }
}

// ---------------------------------------------------------------------------
// Inverse FFT (R9-proven): same structure, conjugate twiddles, residual add.
// ---------------------------------------------------------------------------
__global__ __launch_bounds__(1024) void inv_fft_kernel(const float* __restrict__ x,
                                                       float* __restrict__ y) {
    float2* buf = reinterpret_cast<float2*>(smem_raw);
    float2* tw  = buf + PAIRS_PER_CTA * LSEQ;
    const int tid = threadIdx.x;
    const int sub = tid >> 8;
    const int st  = tid & 255;
    const int bi  = blockIdx.x;
    const int b   = bi / (DCH / 8);
    const int c0  = (bi % (DCH / 8)) * 8;
    const int d0  = c0 + 2 * sub;

    for (int j = tid; j < LSEQ / 2; j += 1024) {
        float sv, cv;
        sincosf(6.28318530717958647692f * (float)j / (float)LSEQ, &sv, &cv);
        tw[j] = make_float2(cv, sv);
    }
    float2* bp = buf + sub * LSEQ;
    const float* SrB = g_Sr + ((size_t)b * DCH + d0) * MP;
    const float* SiB = g_Si + ((size_t)b * DCH + d0) * MP;
    for (int k = st; k < NMODES; k += 256) {
        float ar  = SrB[k],      ai  = SiB[k];
        float br  = SrB[MP + k], bi_ = SiB[MP + k];
        if (k == 0 || k == LSEQ / 2) { ai = 0.0f; bi_ = 0.0f; }
        bp[k] = make_float2(ar - bi_, ai + br);
        if (k > 0 && k < LSEQ / 2)
            bp[LSEQ - k] = make_float2(ar + bi_, br - ai);
    }
    __syncthreads();

    for (int ls = 0; ls < 12; ls++) {
        const int s = 1 << ls;
        float2 a[8], c[8];
        #pragma unroll
        for (int k = 0; k < 8; k++) {
            int bt = st + (k << 8);
            a[k] = bp[bt];
            c[k] = bp[bt + 2048];
        }
        __syncthreads();
        #pragma unroll
        for (int k = 0; k < 8; k++) {
            int bt = st + (k << 8);
            int r  = bt & ~(s - 1);
            float2 w = tw[r];
            float dx = a[k].x - c[k].x, dy = a[k].y - c[k].y;
            int o = bt + r;
            bp[o]     = make_float2(a[k].x + c[k].x, a[k].y + c[k].y);
            bp[o + s] = make_float2(dx * w.x - dy * w.y, dx * w.y + dy * w.x);
        }
        __syncthreads();
    }
    const float sc = 1.0f / 64.0f;
    const float* xs = x + (size_t)b * LSEQ * DCH + c0;
    float*       ys = y + (size_t)b * LSEQ * DCH + c0;
    for (int i = tid; i < LSEQ * 2; i += 1024) {
        int l = i >> 1, h = i & 1;
        float2 u  = buf[(2 * h)     * LSEQ + l];
        float2 v2 = buf[(2 * h + 1) * LSEQ + l];
        float4 xv = *reinterpret_cast<const float4*>(xs + (size_t)l * DCH + h * 4);
        float4 out = make_float4(xv.x + u.x * sc,  xv.y + u.y * sc,
                                 xv.z + v2.x * sc, xv.w + v2.y * sc);
        *reinterpret_cast<float4*>(ys + (size_t)l * DCH + h * 4) = out;
    }
}

// ---------------------------------------------------------------------------
// Per-mode complex block-diagonal MLP, Gauss 3-mult + packed f32x2 FMA.
// R10 shape: 384 threads, lane = tid&15 -> modes lane*8..+7 (4 pairs),
// og = tid>>4 (0..23) -> outputs og*4..+3 (float4 W reads).
// Weight combos precomputed at staging: Wr, Wd = wi-wr, Ws = wr+wi.
// Accumulate A1 += wr*(xr+xi); A2 += (wi-wr)*xr; A3 += (wr+wi)*xi;
// R = A1 - A3, I = A1 + A2 (biases folded into A2/A3 init).
// Per K-step: 48 FFMA2 + 4 FADD2 + 7 LDS.128 + 12 bcast.
// Smem: W 3*36KB + X/O1 96KB = 204KB, 1 CTA/SM.
// ---------------------------------------------------------------------------
__global__ __launch_bounds__(MLP_THREADS) void mlp_kernel(const float* __restrict__ w1,
                                                          const float* __restrict__ b1,
                                                          const float* __restrict__ w2,
                                                          const float* __restrict__ b2) {
    float* Wr = reinterpret_cast<float*>(smem_raw);    // [96][96]
    float* Wd = Wr + BS * BS;                          // wi - wr
    float* Ws = Wd + BS * BS;                          // wr + wi
    float* Xr = Ws + BS * BS;                          // [96][128], reused for O1
    float* Xi = Xr + BS * MT;

    const int tid  = threadIdx.x;
    const int n    = blockIdx.y;
    const int b    = blockIdx.z;
    const int m0   = blockIdx.x * MT;
    const int lane = tid & 15;
    const int og   = tid >> 4;          // 0..23
    const bool full = (m0 + MT <= NMODES);

    // stage W1 with Gauss combos (layout w1[c][n][i][o])
    {
        const float4* w1r4 = reinterpret_cast<const float4*>(w1 + (size_t)n * BS * BS);
        const float4* w1i4 = reinterpret_cast<const float4*>(w1 + (size_t)(NBLK + n) * BS * BS);
        for (int t = tid; t < BS * BS / 4; t += MLP_THREADS) {
            float4 r = w1r4[t], i = w1i4[t];
            reinterpret_cast<float4*>(Wr)[t] = r;
            reinterpret_cast<float4*>(Wd)[t] = make_float4(i.x - r.x, i.y - r.y, i.z - r.z, i.w - r.w);
            reinterpret_cast<float4*>(Ws)[t] = make_float4(i.x + r.x, i.y + r.y, i.z + r.z, i.w + r.w);
        }
    }
    float* SrB = g_Sr + ((size_t)b * DCH + n * BS) * MP;
    float* SiB = g_Si + ((size_t)b * DCH + n * BS) * MP;
    for (int t = tid; t < BS * (MT / 4); t += MLP_THREADS) {
        int i = t >> 5, c = t & 31;
        int m = m0 + c * 4;
        float4 vr, vi;
        if (full) {
            vr = *reinterpret_cast<const float4*>(SrB + (size_t)i * MP + m);
            vi = *reinterpret_cast<const float4*>(SiB + (size_t)i * MP + m);
        } else {
            vr = make_float4(0.f, 0.f, 0.f, 0.f);
            vi = make_float4(0.f, 0.f, 0.f, 0.f);
            #pragma unroll
            for (int j = 0; j < 4; j++) {
                if (m + j < NMODES) {
                    (&vr.x)[j] = SrB[(size_t)i * MP + m + j];
                    (&vi.x)[j] = SiB[(size_t)i * MP + m + j];
                }
            }
        }
        *reinterpret_cast<float4*>(Xr + i * MT + c * 4) = vr;
        *reinterpret_cast<float4*>(Xi + i * MT + c * 4) = vi;
    }
    __syncthreads();

    // ---------------- layer 1 ----------------
    // A1: plain sum; A2 init = +bi (I = A1 + A2); A3 init = -br (R = A1 - A3)
    ull A1[4][4], A2[4][4], A3[4][4];
    {
        const float* b1r = b1 + (size_t)n * BS + og * 4;
        const float* b1i = b1 + (size_t)(NBLK + n) * BS + og * 4;
        #pragma unroll
        for (int oo = 0; oo < 4; oo++) {
            ull vi = bcast2(b1i[oo]), vnr = bcast2(-b1r[oo]);
            #pragma unroll
            for (int j = 0; j < 4; j++) { A1[oo][j] = 0ULL; A2[oo][j] = vi; A3[oo][j] = vnr; }
        }
    }
    {
        const float* xrp = Xr + lane * 8;
        const float* xip = Xi + lane * 8;
        const float* wrp = Wr + og * 4;
        const float* wdp = Wd + og * 4;
        const float* wsp = Ws + og * 4;
        for (int i = 0; i < BS; i++) {
            ulonglong2 xra = *reinterpret_cast<const ulonglong2*>(xrp + i * MT);
            ulonglong2 xrb = *reinterpret_cast<const ulonglong2*>(xrp + i * MT + 4);
            ulonglong2 xia = *reinterpret_cast<const ulonglong2*>(xip + i * MT);
            ulonglong2 xib = *reinterpret_cast<const ulonglong2*>(xip + i * MT + 4);
            ull xr_[4] = {xra.x, xra.y, xrb.x, xrb.y};
            ull xi_[4] = {xia.x, xia.y, xib.x, xib.y};
            ull xs_[4] = {fadd2(xra.x, xia.x), fadd2(xra.y, xia.y),
                          fadd2(xrb.x, xib.x), fadd2(xrb.y, xib.y)};
            float4 wr4 = *reinterpret_cast<const float4*>(wrp + i * BS);
            float4 wd4 = *reinterpret_cast<const float4*>(wdp + i * BS);
            float4 ws4 = *reinterpret_cast<const float4*>(wsp + i * BS);
            const float* wrv = &wr4.x;
            const float* wdv = &wd4.x;
            const float* wsv = &ws4.x;
            #pragma unroll
            for (int oo = 0; oo < 4; oo++) {
                ull w_r = bcast2(wrv[oo]);
                ull w_d = bcast2(wdv[oo]);
                ull w_s = bcast2(wsv[oo]);
                #pragma unroll
                for (int j = 0; j < 4; j++) {
                    ffma2(A1[oo][j], w_r, xs_[j]);
                    ffma2(A2[oo][j], w_d, xr_[j]);
                    ffma2(A3[oo][j], w_s, xi_[j]);
                }
            }
        }
    }
    __syncthreads();   // all X / W1 reads done

    // relu(R = A1 - A3, I = A1 + A2) -> O1 (into X buffer); stage W2
    #pragma unroll
    for (int oo = 0; oo < 4; oo++) {
        int row = og * 4 + oo;
        float r[8], im[8];
        #pragma unroll
        for (int j = 0; j < 4; j++) {
            float a1l, a1h, a2l, a2h, a3l, a3h;
            unpack2(A1[oo][j], a1l, a1h);
            unpack2(A2[oo][j], a2l, a2h);
            unpack2(A3[oo][j], a3l, a3h);
            r[2 * j]      = a1l - a3l;  r[2 * j + 1]  = a1h - a3h;
            im[2 * j]     = a1l + a2l;  im[2 * j + 1] = a1h + a2h;
        }
        *reinterpret_cast<float4*>(Xr + row * MT + lane * 8) =
            make_float4(fmaxf(r[0], 0.f), fmaxf(r[1], 0.f), fmaxf(r[2], 0.f), fmaxf(r[3], 0.f));
        *reinterpret_cast<float4*>(Xr + row * MT + lane * 8 + 4) =
            make_float4(fmaxf(r[4], 0.f), fmaxf(r[5], 0.f), fmaxf(r[6], 0.f), fmaxf(r[7], 0.f));
        *reinterpret_cast<float4*>(Xi + row * MT + lane * 8) =
            make_float4(fmaxf(im[0], 0.f), fmaxf(im[1], 0.f), fmaxf(im[2], 0.f), fmaxf(im[3], 0.f));
        *reinterpret_cast<float4*>(Xi + row * MT + lane * 8 + 4) =
            make_float4(fmaxf(im[4], 0.f), fmaxf(im[5], 0.f), fmaxf(im[6], 0.f), fmaxf(im[7], 0.f));
    }
    {
        const float4* w2r4 = reinterpret_cast<const float4*>(w2 + (size_t)n * BS * BS);
        const float4* w2i4 = reinterpret_cast<const float4*>(w2 + (size_t)(NBLK + n) * BS * BS);
        for (int t = tid; t < BS * BS / 4; t += MLP_THREADS) {
            float4 r = w2r4[t], i = w2i4[t];
            reinterpret_cast<float4*>(Wr)[t] = r;
            reinterpret_cast<float4*>(Wd)[t] = make_float4(i.x - r.x, i.y - r.y, i.z - r.z, i.w - r.w);
            reinterpret_cast<float4*>(Ws)[t] = make_float4(i.x + r.x, i.y + r.y, i.z + r.z, i.w + r.w);
        }
    }
    __syncthreads();

    // ---------------- layer 2 ----------------
    {
        const float* b2r = b2 + (size_t)n * BS + og * 4;
        const float* b2i = b2 + (size_t)(NBLK + n) * BS + og * 4;
        #pragma unroll
        for (int oo = 0; oo < 4; oo++) {
            ull vi = bcast2(b2i[oo]), vnr = bcast2(-b2r[oo]);
            #pragma unroll
            for (int j = 0; j < 4; j++) { A1[oo][j] = 0ULL; A2[oo][j] = vi; A3[oo][j] = vnr; }
        }
    }
    {
        const float* xrp = Xr + lane * 8;
        const float* xip = Xi + lane * 8;
        const float* wrp = Wr + og * 4;
        const float* wdp = Wd + og * 4;
        const float* wsp = Ws + og * 4;
        for (int o = 0; o < BS; o++) {
            ulonglong2 xra = *reinterpret_cast<const ulonglong2*>(xrp + o * MT);
            ulonglong2 xrb = *reinterpret_cast<const ulonglong2*>(xrp + o * MT + 4);
            ulonglong2 xia = *reinterpret_cast<const ulonglong2*>(xip + o * MT);
            ulonglong2 xib = *reinterpret_cast<const ulonglong2*>(xip + o * MT + 4);
            ull xr_[4] = {xra.x, xra.y, xrb.x, xrb.y};
            ull xi_[4] = {xia.x, xia.y, xib.x, xib.y};
            ull xs_[4] = {fadd2(xra.x, xia.x), fadd2(xra.y, xia.y),
                          fadd2(xrb.x, xib.x), fadd2(xrb.y, xib.y)};
            float4 wr4 = *reinterpret_cast<const float4*>(wrp + o * BS);
            float4 wd4 = *reinterpret_cast<const float4*>(wdp + o * BS);
            float4 ws4 = *reinterpret_cast<const float4*>(wsp + o * BS);
            const float* wrv = &wr4.x;
            const float* wdv = &wd4.x;
            const float* wsv = &ws4.x;
            #pragma unroll
            for (int oo = 0; oo < 4; oo++) {
                ull w_r = bcast2(wrv[oo]);
                ull w_d = bcast2(wdv[oo]);
                ull w_s = bcast2(wsv[oo]);
                #pragma unroll
                for (int j = 0; j < 4; j++) {
                    ffma2(A1[oo][j], w_r, xs_[j]);
                    ffma2(A2[oo][j], w_d, xr_[j]);
                    ffma2(A3[oo][j], w_s, xi_[j]);
                }
            }
        }
    }

    // softshrink(R = A1 - A3, I = A1 + A2) + store
    #pragma unroll
    for (int oo = 0; oo < 4; oo++) {
        int row = og * 4 + oo;
        float v[16];
        #pragma unroll
        for (int j = 0; j < 4; j++) {
            float a1l, a1h, a2l, a2h, a3l, a3h;
            unpack2(A1[oo][j], a1l, a1h);
            unpack2(A2[oo][j], a2l, a2h);
            unpack2(A3[oo][j], a3l, a3h);
            v[2 * j]         = a1l - a3l;  v[2 * j + 1]     = a1h - a3h;
            v[8 + 2 * j]     = a1l + a2l;  v[9 + 2 * j]     = a1h + a2h;
        }
        #pragma unroll
        for (int j = 0; j < 16; j++) {
            float t = fabsf(v[j]) - LAMBDA;
            v[j] = t > 0.f ? copysignf(t, v[j]) : 0.f;
        }
        int m = m0 + lane * 8;
        if (full) {
            *reinterpret_cast<float4*>(SrB + (size_t)row * MP + m)     = make_float4(v[0], v[1], v[2], v[3]);
            *reinterpret_cast<float4*>(SrB + (size_t)row * MP + m + 4) = make_float4(v[4], v[5], v[6], v[7]);
            *reinterpret_cast<float4*>(SiB + (size_t)row * MP + m)     = make_float4(v[8], v[9], v[10], v[11]);
            *reinterpret_cast<float4*>(SiB + (size_t)row * MP + m + 4) = make_float4(v[12], v[13], v[14], v[15]);
        } else {
            #pragma unroll
            for (int j = 0; j < 8; j++) {
                if (m + j < NMODES) {
                    SrB[(size_t)row * MP + m + j] = v[j];
                    SiB[(size_t)row * MP + m + j] = v[8 + j];
                }
            }
        }
    }
}

// ---------------------------------------------------------------------------
extern "C" void kernel_launch(void* const* d_in, const int* in_sizes, int n_in,
                              void* d_out, int out_size) {
    const float* x  = (const float*)d_in[0];
    const float* w1 = (const float*)d_in[1];
    const float* b1 = (const float*)d_in[2];
    const float* w2 = (const float*)d_in[3];
    const float* b2 = (const float*)d_in[4];
    float* y = (float*)d_out;

    const size_t fft_smem = (size_t)(PAIRS_PER_CTA * LSEQ + LSEQ / 2) * sizeof(float2); // 147456
    const size_t mlp_smem = (size_t)(3 * BS * BS + 2 * BS * MT) * sizeof(float);        // 208896

    cudaFuncSetAttribute(fwd_fft_kernel, cudaFuncAttributeMaxDynamicSharedMemorySize, (int)fft_smem);
    cudaFuncSetAttribute(inv_fft_kernel, cudaFuncAttributeMaxDynamicSharedMemorySize, (int)fft_smem);
    cudaFuncSetAttribute(mlp_kernel,     cudaFuncAttributeMaxDynamicSharedMemorySize, (int)mlp_smem);

    fwd_fft_kernel<<<NBATCH * DCH / 8, 1024, fft_smem>>>(x);

    dim3 g((NMODES + MT - 1) / MT, NBLK, NBATCH);
    mlp_kernel<<<g, MLP_THREADS, mlp_smem>>>(w1, b1, w2, b2);

    inv_fft_kernel<<<NBATCH * DCH / 8, 1024, fft_smem>>>(x, y);
}

// round 14
// speedup vs baseline: 1.2231x; 1.0871x over previous
#include <cuda_runtime.h>
#include <math.h>

#define LSEQ   4096
#define DCH    768
#define NBATCH 8
#define NBLK   8
#define BS     96
#define NMODES 2049   // LSEQ/2 + 1
#define MP     2064   // padded mode stride
#define MT     128    // mode tile in MLP kernel
#define LAMBDA 0.01f
#define PAIRS_PER_CTA 4
#define MLP_THREADS 384

// Scratch spectra: (B, D, MP) real and imag
__device__ float g_Sr[(size_t)NBATCH * DCH * MP];
__device__ float g_Si[(size_t)NBATCH * DCH * MP];

extern __shared__ char smem_raw[];

// ---------------- packed f32x2 helpers (FFMA2 path) ----------------
typedef unsigned long long ull;

__device__ __forceinline__ ull bcast2(float v) {
    ull r; asm("mov.b64 %0, {%1, %1};" : "=l"(r) : "f"(v)); return r;
}
__device__ __forceinline__ void unpack2(ull a, float& lo, float& hi) {
    asm("mov.b64 {%0, %1}, %2;" : "=f"(lo), "=f"(hi) : "l"(a));
}
__device__ __forceinline__ void ffma2(ull& d, ull a, ull b) {
    asm("fma.rn.f32x2 %0, %1, %2, %0;" : "+l"(d) : "l"(a), "l"(b));
}
__device__ __forceinline__ ull fadd2(ull a, ull b) {
    ull r; asm("add.rn.f32x2 %0, %1, %2;" : "=l"(r) : "l"(a), "l"(b)); return r;
}

// ---------------------------------------------------------------------------
// Forward FFT (R9-proven): 4 channel-pairs per CTA, 1024 threads.
// Radix-2 Stockham, 12 stages, single buffer per pair (read/sync/write).
// ---------------------------------------------------------------------------
__global__ __launch_bounds__(1024) void fwd_fft_kernel(const float* __restrict__ x) {
    float2* buf = reinterpret_cast<float2*>(smem_raw);       // [4][4096]
    float2* tw  = buf + PAIRS_PER_CTA * LSEQ;                // [2048]
    const int tid = threadIdx.x;
    const int sub = tid >> 8;
    const int st  = tid & 255;
    const int bi  = blockIdx.x;
    const int b   = bi / (DCH / 8);
    const int c0  = (bi % (DCH / 8)) * 8;

    for (int j = tid; j < LSEQ / 2; j += 1024) {
        float sv, cv;
        sincosf(-6.28318530717958647692f * (float)j / (float)LSEQ, &sv, &cv);
        tw[j] = make_float2(cv, sv);
    }
    const float* xs = x + (size_t)b * LSEQ * DCH + c0;
    for (int i = tid; i < LSEQ * 2; i += 1024) {
        int l = i >> 1, h = i & 1;
        float4 v = *reinterpret_cast<const float4*>(xs + (size_t)l * DCH + h * 4);
        buf[(2 * h)     * LSEQ + l] = make_float2(v.x, v.y);
        buf[(2 * h + 1) * LSEQ + l] = make_float2(v.z, v.w);
    }
    __syncthreads();

    float2* bp = buf + sub * LSEQ;
    for (int ls = 0; ls < 12; ls++) {
        const int s = 1 << ls;
        float2 a[8], c[8];
        #pragma unroll
        for (int k = 0; k < 8; k++) {
            int bt = st + (k << 8);
            a[k] = bp[bt];
            c[k] = bp[bt + 2048];
        }
        __syncthreads();
        #pragma unroll
        for (int k = 0; k < 8; k++) {
            int bt = st + (k << 8);
            int r  = bt & ~(s - 1);
            float2 w = tw[r];
            float dx = a[k].x - c[k].x, dy = a[k].y - c[k].y;
            int o = bt + r;
            bp[o]     = make_float2(a[k].x + c[k].x, a[k].y + c[k].y);
            bp[o + s] = make_float2(dx * w.x - dy * w.y, dx * w.y + dy * w.x);
        }
        __syncthreads();
    }
    const int d0 = c0 + 2 * sub;
    const float scale = 0.5f / 64.0f;
    float* SrB = g_Sr + ((size_t)b * DCH + d0) * MP;
    float* SiB = g_Si + ((size_t)b * DCH + d0) * MP;
    for (int k = st; k < NMODES; k += 256) {
        float2 z1 = bp[k];
        float2 z2 = bp[(LSEQ - k) & (LSEQ - 1)];
        SrB[k]      = (z1.x + z2.x) * scale;
        SiB[k]      = (z1.y - z2.y) * scale;
        SrB[MP + k] = (z1.y + z2.y) * scale;
        SiB[MP + k] = (z2.x - z1.x) * scale;
    }
}

// ---------------------------------------------------------------------------
// Inverse FFT (R9-proven): same structure, conjugate twiddles, residual add.
// ---------------------------------------------------------------------------
__global__ __launch_bounds__(1024) void inv_fft_kernel(const float* __restrict__ x,
                                                       float* __restrict__ y) {
    float2* buf = reinterpret_cast<float2*>(smem_raw);
    float2* tw  = buf + PAIRS_PER_CTA * LSEQ;
    const int tid = threadIdx.x;
    const int sub = tid >> 8;
    const int st  = tid & 255;
    const int bi  = blockIdx.x;
    const int b   = bi / (DCH / 8);
    const int c0  = (bi % (DCH / 8)) * 8;
    const int d0  = c0 + 2 * sub;

    for (int j = tid; j < LSEQ / 2; j += 1024) {
        float sv, cv;
        sincosf(6.28318530717958647692f * (float)j / (float)LSEQ, &sv, &cv);
        tw[j] = make_float2(cv, sv);
    }
    float2* bp = buf + sub * LSEQ;
    const float* SrB = g_Sr + ((size_t)b * DCH + d0) * MP;
    const float* SiB = g_Si + ((size_t)b * DCH + d0) * MP;
    for (int k = st; k < NMODES; k += 256) {
        float ar  = SrB[k],      ai  = SiB[k];
        float br  = SrB[MP + k], bi_ = SiB[MP + k];
        if (k == 0 || k == LSEQ / 2) { ai = 0.0f; bi_ = 0.0f; }
        bp[k] = make_float2(ar - bi_, ai + br);
        if (k > 0 && k < LSEQ / 2)
            bp[LSEQ - k] = make_float2(ar + bi_, br - ai);
    }
    __syncthreads();

    for (int ls = 0; ls < 12; ls++) {
        const int s = 1 << ls;
        float2 a[8], c[8];
        #pragma unroll
        for (int k = 0; k < 8; k++) {
            int bt = st + (k << 8);
            a[k] = bp[bt];
            c[k] = bp[bt + 2048];
        }
        __syncthreads();
        #pragma unroll
        for (int k = 0; k < 8; k++) {
            int bt = st + (k << 8);
            int r  = bt & ~(s - 1);
            float2 w = tw[r];
            float dx = a[k].x - c[k].x, dy = a[k].y - c[k].y;
            int o = bt + r;
            bp[o]     = make_float2(a[k].x + c[k].x, a[k].y + c[k].y);
            bp[o + s] = make_float2(dx * w.x - dy * w.y, dx * w.y + dy * w.x);
        }
        __syncthreads();
    }
    const float sc = 1.0f / 64.0f;
    const float* xs = x + (size_t)b * LSEQ * DCH + c0;
    float*       ys = y + (size_t)b * LSEQ * DCH + c0;
    for (int i = tid; i < LSEQ * 2; i += 1024) {
        int l = i >> 1, h = i & 1;
        float2 u  = buf[(2 * h)     * LSEQ + l];
        float2 v2 = buf[(2 * h + 1) * LSEQ + l];
        float4 xv = *reinterpret_cast<const float4*>(xs + (size_t)l * DCH + h * 4);
        float4 out = make_float4(xv.x + u.x * sc,  xv.y + u.y * sc,
                                 xv.z + v2.x * sc, xv.w + v2.y * sc);
        *reinterpret_cast<float4*>(ys + (size_t)l * DCH + h * 4) = out;
    }
}

// ---------------------------------------------------------------------------
// Per-mode complex block-diagonal MLP, Gauss 3-mult + packed f32x2 FMA.
// 384 threads. lane = tid&15 -> modes {lane*4..+3, 64+lane*4..+3} (dense
// float4 accesses at lane*16B: conflict-free, 2 wavefronts per LDS.128).
// og = tid>>4 (0..23) -> outputs og*4..+3 (float4 W reads).
// Gauss: A1 += wr*(xr+xi); A2 += (wi-wr)*xr; A3 += (wr+wi)*xi;
// R = A1 - A3, I = A1 + A2 (biases folded into A2/A3 init).
// Smem: W 3*36KB + X/O1 96KB = 204KB, 1 CTA/SM.
// ---------------------------------------------------------------------------
__global__ __launch_bounds__(MLP_THREADS) void mlp_kernel(const float* __restrict__ w1,
                                                          const float* __restrict__ b1,
                                                          const float* __restrict__ w2,
                                                          const float* __restrict__ b2) {
    float* Wr = reinterpret_cast<float*>(smem_raw);    // [96][96]
    float* Wd = Wr + BS * BS;                          // wi - wr
    float* Ws = Wd + BS * BS;                          // wr + wi
    float* Xr = Ws + BS * BS;                          // [96][128], reused for O1
    float* Xi = Xr + BS * MT;

    const int tid  = threadIdx.x;
    const int n    = blockIdx.y;
    const int b    = blockIdx.z;
    const int m0   = blockIdx.x * MT;
    const int lane = tid & 15;
    const int og   = tid >> 4;          // 0..23
    const bool full = (m0 + MT <= NMODES);

    // stage W1 with Gauss combos (layout w1[c][n][i][o])
    {
        const float4* w1r4 = reinterpret_cast<const float4*>(w1 + (size_t)n * BS * BS);
        const float4* w1i4 = reinterpret_cast<const float4*>(w1 + (size_t)(NBLK + n) * BS * BS);
        for (int t = tid; t < BS * BS / 4; t += MLP_THREADS) {
            float4 r = w1r4[t], i = w1i4[t];
            reinterpret_cast<float4*>(Wr)[t] = r;
            reinterpret_cast<float4*>(Wd)[t] = make_float4(i.x - r.x, i.y - r.y, i.z - r.z, i.w - r.w);
            reinterpret_cast<float4*>(Ws)[t] = make_float4(i.x + r.x, i.y + r.y, i.z + r.z, i.w + r.w);
        }
    }
    float* SrB = g_Sr + ((size_t)b * DCH + n * BS) * MP;
    float* SiB = g_Si + ((size_t)b * DCH + n * BS) * MP;
    for (int t = tid; t < BS * (MT / 4); t += MLP_THREADS) {
        int i = t >> 5, c = t & 31;
        int m = m0 + c * 4;
        float4 vr, vi;
        if (full) {
            vr = *reinterpret_cast<const float4*>(SrB + (size_t)i * MP + m);
            vi = *reinterpret_cast<const float4*>(SiB + (size_t)i * MP + m);
        } else {
            vr = make_float4(0.f, 0.f, 0.f, 0.f);
            vi = make_float4(0.f, 0.f, 0.f, 0.f);
            #pragma unroll
            for (int j = 0; j < 4; j++) {
                if (m + j < NMODES) {
                    (&vr.x)[j] = SrB[(size_t)i * MP + m + j];
                    (&vi.x)[j] = SiB[(size_t)i * MP + m + j];
                }
            }
        }
        *reinterpret_cast<float4*>(Xr + i * MT + c * 4) = vr;
        *reinterpret_cast<float4*>(Xi + i * MT + c * 4) = vi;
    }
    __syncthreads();

    // ---------------- layer 1 ----------------
    // acc pairs: j=0,1 -> modes lane*4..+3 ; j=2,3 -> modes 64+lane*4..+3
    ull A1[4][4], A2[4][4], A3[4][4];
    {
        const float* b1r = b1 + (size_t)n * BS + og * 4;
        const float* b1i = b1 + (size_t)(NBLK + n) * BS + og * 4;
        #pragma unroll
        for (int oo = 0; oo < 4; oo++) {
            ull vi = bcast2(b1i[oo]), vnr = bcast2(-b1r[oo]);
            #pragma unroll
            for (int j = 0; j < 4; j++) { A1[oo][j] = 0ULL; A2[oo][j] = vi; A3[oo][j] = vnr; }
        }
    }
    {
        const float* xrp = Xr + lane * 4;
        const float* xip = Xi + lane * 4;
        const float* wrp = Wr + og * 4;
        const float* wdp = Wd + og * 4;
        const float* wsp = Ws + og * 4;
        for (int i = 0; i < BS; i++) {
            ulonglong2 xra = *reinterpret_cast<const ulonglong2*>(xrp + i * MT);
            ulonglong2 xrb = *reinterpret_cast<const ulonglong2*>(xrp + i * MT + 64);
            ulonglong2 xia = *reinterpret_cast<const ulonglong2*>(xip + i * MT);
            ulonglong2 xib = *reinterpret_cast<const ulonglong2*>(xip + i * MT + 64);
            ull xr_[4] = {xra.x, xra.y, xrb.x, xrb.y};
            ull xi_[4] = {xia.x, xia.y, xib.x, xib.y};
            ull xs_[4] = {fadd2(xra.x, xia.x), fadd2(xra.y, xia.y),
                          fadd2(xrb.x, xib.x), fadd2(xrb.y, xib.y)};
            float4 wr4 = *reinterpret_cast<const float4*>(wrp + i * BS);
            float4 wd4 = *reinterpret_cast<const float4*>(wdp + i * BS);
            float4 ws4 = *reinterpret_cast<const float4*>(wsp + i * BS);
            const float* wrv = &wr4.x;
            const float* wdv = &wd4.x;
            const float* wsv = &ws4.x;
            #pragma unroll
            for (int oo = 0; oo < 4; oo++) {
                ull w_r = bcast2(wrv[oo]);
                ull w_d = bcast2(wdv[oo]);
                ull w_s = bcast2(wsv[oo]);
                #pragma unroll
                for (int j = 0; j < 4; j++) {
                    ffma2(A1[oo][j], w_r, xs_[j]);
                    ffma2(A2[oo][j], w_d, xr_[j]);
                    ffma2(A3[oo][j], w_s, xi_[j]);
                }
            }
        }
    }
    __syncthreads();   // all X / W1 reads done

    // relu(R = A1 - A3, I = A1 + A2) -> O1 (into X buffer); stage W2
    #pragma unroll
    for (int oo = 0; oo < 4; oo++) {
        int row = og * 4 + oo;
        float r[8], im[8];
        #pragma unroll
        for (int j = 0; j < 4; j++) {
            float a1l, a1h, a2l, a2h, a3l, a3h;
            unpack2(A1[oo][j], a1l, a1h);
            unpack2(A2[oo][j], a2l, a2h);
            unpack2(A3[oo][j], a3l, a3h);
            r[2 * j]      = a1l - a3l;  r[2 * j + 1]  = a1h - a3h;
            im[2 * j]     = a1l + a2l;  im[2 * j + 1] = a1h + a2h;
        }
        *reinterpret_cast<float4*>(Xr + row * MT + lane * 4) =
            make_float4(fmaxf(r[0], 0.f), fmaxf(r[1], 0.f), fmaxf(r[2], 0.f), fmaxf(r[3], 0.f));
        *reinterpret_cast<float4*>(Xr + row * MT + 64 + lane * 4) =
            make_float4(fmaxf(r[4], 0.f), fmaxf(r[5], 0.f), fmaxf(r[6], 0.f), fmaxf(r[7], 0.f));
        *reinterpret_cast<float4*>(Xi + row * MT + lane * 4) =
            make_float4(fmaxf(im[0], 0.f), fmaxf(im[1], 0.f), fmaxf(im[2], 0.f), fmaxf(im[3], 0.f));
        *reinterpret_cast<float4*>(Xi + row * MT + 64 + lane * 4) =
            make_float4(fmaxf(im[4], 0.f), fmaxf(im[5], 0.f), fmaxf(im[6], 0.f), fmaxf(im[7], 0.f));
    }
    {
        const float4* w2r4 = reinterpret_cast<const float4*>(w2 + (size_t)n * BS * BS);
        const float4* w2i4 = reinterpret_cast<const float4*>(w2 + (size_t)(NBLK + n) * BS * BS);
        for (int t = tid; t < BS * BS / 4; t += MLP_THREADS) {
            float4 r = w2r4[t], i = w2i4[t];
            reinterpret_cast<float4*>(Wr)[t] = r;
            reinterpret_cast<float4*>(Wd)[t] = make_float4(i.x - r.x, i.y - r.y, i.z - r.z, i.w - r.w);
            reinterpret_cast<float4*>(Ws)[t] = make_float4(i.x + r.x, i.y + r.y, i.z + r.z, i.w + r.w);
        }
    }
    __syncthreads();

    // ---------------- layer 2 ----------------
    {
        const float* b2r = b2 + (size_t)n * BS + og * 4;
        const float* b2i = b2 + (size_t)(NBLK + n) * BS + og * 4;
        #pragma unroll
        for (int oo = 0; oo < 4; oo++) {
            ull vi = bcast2(b2i[oo]), vnr = bcast2(-b2r[oo]);
            #pragma unroll
            for (int j = 0; j < 4; j++) { A1[oo][j] = 0ULL; A2[oo][j] = vi; A3[oo][j] = vnr; }
        }
    }
    {
        const float* xrp = Xr + lane * 4;
        const float* xip = Xi + lane * 4;
        const float* wrp = Wr + og * 4;
        const float* wdp = Wd + og * 4;
        const float* wsp = Ws + og * 4;
        for (int o = 0; o < BS; o++) {
            ulonglong2 xra = *reinterpret_cast<const ulonglong2*>(xrp + o * MT);
            ulonglong2 xrb = *reinterpret_cast<const ulonglong2*>(xrp + o * MT + 64);
            ulonglong2 xia = *reinterpret_cast<const ulonglong2*>(xip + o * MT);
            ulonglong2 xib = *reinterpret_cast<const ulonglong2*>(xip + o * MT + 64);
            ull xr_[4] = {xra.x, xra.y, xrb.x, xrb.y};
            ull xi_[4] = {xia.x, xia.y, xib.x, xib.y};
            ull xs_[4] = {fadd2(xra.x, xia.x), fadd2(xra.y, xia.y),
                          fadd2(xrb.x, xib.x), fadd2(xrb.y, xib.y)};
            float4 wr4 = *reinterpret_cast<const float4*>(wrp + o * BS);
            float4 wd4 = *reinterpret_cast<const float4*>(wdp + o * BS);
            float4 ws4 = *reinterpret_cast<const float4*>(wsp + o * BS);
            const float* wrv = &wr4.x;
            const float* wdv = &wd4.x;
            const float* wsv = &ws4.x;
            #pragma unroll
            for (int oo = 0; oo < 4; oo++) {
                ull w_r = bcast2(wrv[oo]);
                ull w_d = bcast2(wdv[oo]);
                ull w_s = bcast2(wsv[oo]);
                #pragma unroll
                for (int j = 0; j < 4; j++) {
                    ffma2(A1[oo][j], w_r, xs_[j]);
                    ffma2(A2[oo][j], w_d, xr_[j]);
                    ffma2(A3[oo][j], w_s, xi_[j]);
                }
            }
        }
    }

    // softshrink(R = A1 - A3, I = A1 + A2) + store
    #pragma unroll
    for (int oo = 0; oo < 4; oo++) {
        int row = og * 4 + oo;
        float v[16];   // [0..7] = R for modes A(0..3),B(0..3); [8..15] = I
        #pragma unroll
        for (int j = 0; j < 4; j++) {
            float a1l, a1h, a2l, a2h, a3l, a3h;
            unpack2(A1[oo][j], a1l, a1h);
            unpack2(A2[oo][j], a2l, a2h);
            unpack2(A3[oo][j], a3l, a3h);
            v[2 * j]         = a1l - a3l;  v[2 * j + 1]     = a1h - a3h;
            v[8 + 2 * j]     = a1l + a2l;  v[9 + 2 * j]     = a1h + a2h;
        }
        #pragma unroll
        for (int j = 0; j < 16; j++) {
            float t = fabsf(v[j]) - LAMBDA;
            v[j] = t > 0.f ? copysignf(t, v[j]) : 0.f;
        }
        int mA = m0 + lane * 4;
        int mB = m0 + 64 + lane * 4;
        if (full) {
            *reinterpret_cast<float4*>(SrB + (size_t)row * MP + mA) = make_float4(v[0], v[1], v[2], v[3]);
            *reinterpret_cast<float4*>(SrB + (size_t)row * MP + mB) = make_float4(v[4], v[5], v[6], v[7]);
            *reinterpret_cast<float4*>(SiB + (size_t)row * MP + mA) = make_float4(v[8], v[9], v[10], v[11]);
            *reinterpret_cast<float4*>(SiB + (size_t)row * MP + mB) = make_float4(v[12], v[13], v[14], v[15]);
        } else {
            #pragma unroll
            for (int j = 0; j < 4; j++) {
                if (mA + j < NMODES) {
                    SrB[(size_t)row * MP + mA + j] = v[j];
                    SiB[(size_t)row * MP + mA + j] = v[8 + j];
                }
                if (mB + j < NMODES) {
                    SrB[(size_t)row * MP + mB + j] = v[4 + j];
                    SiB[(size_t)row * MP + mB + j] = v[12 + j];
                }
            }
        }
    }
}

// ---------------------------------------------------------------------------
extern "C" void kernel_launch(void* const* d_in, const int* in_sizes, int n_in,
                              void* d_out, int out_size) {
    const float* x  = (const float*)d_in[0];
    const float* w1 = (const float*)d_in[1];
    const float* b1 = (const float*)d_in[2];
    const float* w2 = (const float*)d_in[3];
    const float* b2 = (const float*)d_in[4];
    float* y = (float*)d_out;

    const size_t fft_smem = (size_t)(PAIRS_PER_CTA * LSEQ + LSEQ / 2) * sizeof(float2); // 147456
    const size_t mlp_smem = (size_t)(3 * BS * BS + 2 * BS * MT) * sizeof(float);        // 208896

    cudaFuncSetAttribute(fwd_fft_kernel, cudaFuncAttributeMaxDynamicSharedMemorySize, (int)fft_smem);
    cudaFuncSetAttribute(inv_fft_kernel, cudaFuncAttributeMaxDynamicSharedMemorySize, (int)fft_smem);
    cudaFuncSetAttribute(mlp_kernel,     cudaFuncAttributeMaxDynamicSharedMemorySize, (int)mlp_smem);

    fwd_fft_kernel<<<NBATCH * DCH / 8, 1024, fft_smem>>>(x);

    dim3 g((NMODES + MT - 1) / MT, NBLK, NBATCH);
    mlp_kernel<<<g, MLP_THREADS, mlp_smem>>>(w1, b1, w2, b2);

    inv_fft_kernel<<<NBATCH * DCH / 8, 1024, fft_smem>>>(x, y);
}